// round 8
// baseline (speedup 1.0000x reference)
#include <cuda_runtime.h>
#include <cmath>
#include <stdint.h>

#define NLEV   16
#define NDENSE 5
#define TSIZE  (1u << 19)
#define HID    64
#define ENC    32
#define P2     2654435761u
#define P3     805459861u
#define NMAX   1048576
#define NBINS  32768

#define BLK    160          // threads per CTA
#define PTS    320          // points per CTA (2 per thread)

typedef unsigned long long u64;

// ---- device scratch (static, no runtime allocation) ----
#define QCAP 339072
__device__ float4 g_Q[QCAP];          // dense-level x-pair tables
__device__ int    g_hist[NBINS];      // morton histogram / running offsets
__device__ float4 g_xs[NMAX];         // sorted (x01, y01, z01, orig_idx)

struct LevelParams {
    float    resf[NLEV];
    unsigned s1[NLEV];
    unsigned s2[NLEV];
    unsigned qoff[NDENSE];
    unsigned qcnt[NDENSE];
};

__device__ __forceinline__ u64 pk2(float a, float b) {
    u64 r; asm("mov.b64 %0, {%1,%2};" : "=l"(r) : "f"(a), "f"(b)); return r;
}
__device__ __forceinline__ void upk2(u64 v, float& a, float& b) {
    asm("mov.b64 {%0,%1}, %2;" : "=f"(a), "=f"(b) : "l"(v));
}
// Blackwell packed fp32 FMA (FFMA2), only reachable via PTX.
__device__ __forceinline__ u64 ffma2(u64 a, u64 b, u64 c) {
    u64 d; asm("fma.rn.f32x2 %0, %1, %2, %3;" : "=l"(d) : "l"(a), "l"(b), "l"(c)); return d;
}

// ---------- dense pair tables ----------
__global__ void build_q(const float2* __restrict__ tables, LevelParams lp, unsigned total) {
    unsigned i = blockIdx.x * blockDim.x + threadIdx.x;
    if (i >= total) return;
    int l = 0; unsigned base = 0;
#pragma unroll
    for (int k = 0; k < NDENSE; k++) {
        unsigned o = lp.qoff[k];
        if (i >= o && i < o + lp.qcnt[k]) { l = k; base = o; }
    }
    unsigned j = i - base;
    const float2* __restrict__ tab = tables + (size_t)l * TSIZE;
    float2 a = __ldg(&tab[j]);
    float2 b = __ldg(&tab[j + 1]);
    g_Q[i] = make_float4(a.x, a.y, b.x, b.y);
}

// ---------- morton binning ----------
__device__ __forceinline__ unsigned part3(unsigned v) {
    v &= 31u;
    unsigned r = 0;
#pragma unroll
    for (int b = 0; b < 5; b++) r |= ((v >> b) & 1u) << (3 * b);
    return r;
}
__device__ __forceinline__ unsigned morton_bin(float x0, float y0, float z0) {
    unsigned bx = min(31, max(0, (int)floorf(x0 * 32.0f)));
    unsigned by = min(31, max(0, (int)floorf(y0 * 32.0f)));
    unsigned bz = min(31, max(0, (int)floorf(z0 * 32.0f)));
    return part3(bx) | (part3(by) << 1) | (part3(bz) << 2);
}

__global__ void bin_points(const float* __restrict__ x, int npts) {
    int p = blockIdx.x * blockDim.x + threadIdx.x;
    if (p >= npts) return;
    float x0 = (x[3 * p + 0] + 1.0f) * 0.5f;
    float y0 = (x[3 * p + 1] + 1.0f) * 0.5f;
    float z0 = (x[3 * p + 2] + 1.0f) * 0.5f;
    atomicAdd(&g_hist[morton_bin(x0, y0, z0)], 1);
}

// exclusive prefix sum over NBINS (single block, 1024 threads, 32 bins each)
__global__ void scan_bins() {
    __shared__ int warp_tot[32];
    const int t = threadIdx.x;
    const int base = t * (NBINS / 1024);
    int loc[NBINS / 1024];
    int ts = 0;
#pragma unroll
    for (int k = 0; k < NBINS / 1024; k++) { loc[k] = g_hist[base + k]; ts += loc[k]; }
    int v = ts;
    for (int d = 1; d < 32; d <<= 1) {
        int n = __shfl_up_sync(0xffffffffu, v, d);
        if ((t & 31) >= d) v += n;
    }
    if ((t & 31) == 31) warp_tot[t >> 5] = v;
    __syncthreads();
    if (t < 32) {
        int w = warp_tot[t];
        for (int d = 1; d < 32; d <<= 1) {
            int n = __shfl_up_sync(0xffffffffu, w, d);
            if (t >= d) w += n;
        }
        warp_tot[t] = w;
    }
    __syncthreads();
    int excl = v - ts + ((t >> 5) ? warp_tot[(t >> 5) - 1] : 0);
    int run = excl;
#pragma unroll
    for (int k = 0; k < NBINS / 1024; k++) { g_hist[base + k] = run; run += loc[k]; }
}

__global__ void scatter_points(const float* __restrict__ x, int npts) {
    int p = blockIdx.x * blockDim.x + threadIdx.x;
    if (p >= npts) return;
    float x0 = (x[3 * p + 0] + 1.0f) * 0.5f;
    float y0 = (x[3 * p + 1] + 1.0f) * 0.5f;
    float z0 = (x[3 * p + 2] + 1.0f) * 0.5f;
    int pos = atomicAdd(&g_hist[morton_bin(x0, y0, z0)], 1);
    g_xs[pos] = make_float4(x0, y0, z0, __int_as_float(p));
}

// ---------- main fused kernel: 160 threads, 320 points/block (2 per thread) ----------
// smem = weights(24.25K) + sH(64x320 f32 = 80K) ~ 104.25KB -> 2 CTAs / 10 warps per SM.
// Weight LDS amortized over 2 points per thread; all sH accesses column-private
// (no syncs after the weight-load barrier).
__global__ void __launch_bounds__(BLK, 2) sdf_fused(
    const float* __restrict__ tables,
    const float* __restrict__ W0,
    const float* __restrict__ W1,
    const float* __restrict__ W2,
    float* __restrict__ out,
    int npts, LevelParams lp)
{
    extern __shared__ __align__(16) float smem[];
    float* sW0 = smem;                       // 2048 floats
    float* sW1 = sW0 + ENC * HID;            // 4096
    float* sW2 = sW1 + HID * HID;            // 64
    float* sH  = sW2 + HID;                  // 64*PTS (enc phase uses first 32 rows)

    {
        int t = threadIdx.x;
        float4*       s0 = (float4*)sW0;  const float4* g0 = (const float4*)W0;
        for (int i = t; i < ENC * HID / 4; i += BLK) s0[i] = g0[i];
        float4*       s1 = (float4*)sW1;  const float4* g1 = (const float4*)W1;
        for (int i = t; i < HID * HID / 4; i += BLK) s1[i] = g1[i];
        if (t < HID / 4) ((float4*)sW2)[t] = ((const float4*)W2)[t];
    }
    __syncthreads();

    const int t = threadIdx.x;
    const int base = blockIdx.x * PTS;
    int orig0 = -1, orig1 = -1;

    // ================= gather phase: both points, enc -> smem =================
#pragma unroll 1
    for (int ph = 0; ph < 2; ph++) {
        const int pt = base + ph * BLK + t;
        const int col = ph * BLK + t;
        if (pt >= npts) continue;
        const float4 xs = g_xs[pt];
        if (ph == 0) orig0 = __float_as_int(xs.w); else orig1 = __float_as_int(xs.w);
        const float x0 = xs.x, y0 = xs.y, z0 = xs.z;

        // dense levels
#pragma unroll
        for (int l = 0; l < NDENSE; l++) {
            const float rf = lp.resf[l];
            const float px = x0 * rf, py = y0 * rf, pz = z0 * rf;
            const float fpx = floorf(px), fpy = floorf(py), fpz = floorf(pz);
            const float fx = px - fpx, fy = py - fpy, fz = pz - fpz;
            const unsigned cx = (unsigned)fpx, cy = (unsigned)fpy, cz = (unsigned)fpz;

            const unsigned s1 = lp.s1[l], s2 = lp.s2[l];
            const float4* __restrict__ Q = g_Q + lp.qoff[l];
            const unsigned b0 = cx + cy * s1 + cz * s2;
            const unsigned bb[4] = {b0, b0 + s2, b0 + s1, b0 + s1 + s2};

            float4 q[4];
#pragma unroll
            for (int j = 0; j < 4; j++) q[j] = __ldg(&Q[bb[j]]);

            const float gx = 1.0f - fx, gy = 1.0f - fy, gz = 1.0f - fz;
            const float wyz[4] = {gy * gz, gy * fz, fy * gz, fy * fz};
            float e0 = 0.0f, e1 = 0.0f;
#pragma unroll
            for (int j = 0; j < 4; j++) {
                const float w0 = wyz[j] * gx, w1 = wyz[j] * fx;
                e0 = fmaf(w0, q[j].x, fmaf(w1, q[j].z, e0));
                e1 = fmaf(w0, q[j].y, fmaf(w1, q[j].w, e1));
            }
            sH[(2 * l) * PTS + col] = e0;
            sH[(2 * l + 1) * PTS + col] = e1;
        }

        // hashed levels
#pragma unroll 1
        for (int l = NDENSE; l < NLEV; l++) {
            const float rf = lp.resf[l];
            const float px = x0 * rf, py = y0 * rf, pz = z0 * rf;
            const float fpx = floorf(px), fpy = floorf(py), fpz = floorf(pz);
            const float fx = px - fpx, fy = py - fpy, fz = pz - fpz;
            const unsigned cx = (unsigned)fpx, cy = (unsigned)fpy, cz = (unsigned)fpz;

            const float2* __restrict__ tab2 = ((const float2*)tables) + (size_t)l * TSIZE;
            const float4* __restrict__ tab4 = (const float4*)tab2;
            const unsigned m = TSIZE - 1u;
            const unsigned ay0 = cy * P2, az0 = cz * P3;
            const unsigned s[4] = {ay0 ^ az0, ay0 ^ (az0 + P3),
                                   (ay0 + P2) ^ az0, (ay0 + P2) ^ (az0 + P3)};

            float2 f0[4], f1[4];
            if ((cx & 1u) == 0u) {
#pragma unroll
                for (int j = 0; j < 4; j++) {
                    const unsigned i0 = (cx ^ s[j]) & m;
                    const float4 q = __ldg(&tab4[i0 >> 1]);
                    const bool hi = (i0 & 1u) != 0u;
                    f0[j] = hi ? make_float2(q.z, q.w) : make_float2(q.x, q.y);
                    f1[j] = hi ? make_float2(q.x, q.y) : make_float2(q.z, q.w);
                }
            } else {
                const unsigned cx1 = cx + 1u;
#pragma unroll
                for (int j = 0; j < 4; j++) {
                    f0[j] = __ldg(&tab2[(cx  ^ s[j]) & m]);
                    f1[j] = __ldg(&tab2[(cx1 ^ s[j]) & m]);
                }
            }

            const float gx = 1.0f - fx, gy = 1.0f - fy, gz = 1.0f - fz;
            const float wyz[4] = {gy * gz, gy * fz, fy * gz, fy * fz};
            float e0 = 0.0f, e1 = 0.0f;
#pragma unroll
            for (int j = 0; j < 4; j++) {
                const float w0 = wyz[j] * gx, w1 = wyz[j] * fx;
                e0 = fmaf(w0, f0[j].x, fmaf(w1, f1[j].x, e0));
                e1 = fmaf(w0, f0[j].y, fmaf(w1, f1[j].y, e1));
            }
            sH[(2 * l) * PTS + col] = e0;
            sH[(2 * l + 1) * PTS + col] = e1;
        }
    }

    // ================= layer 0: weight-shared across both points =================
    u64 accA[HID / 2], accB[HID / 2];
#pragma unroll
    for (int j = 0; j < HID / 2; j++) { accA[j] = 0ull; accB[j] = 0ull; }

#pragma unroll 2
    for (int e = 0; e < ENC; e++) {
        const float hA = sH[e * PTS + t];
        const float hB = sH[e * PTS + BLK + t];
        const u64 aA = pk2(hA, hA), aB = pk2(hB, hB);
        const ulonglong2* __restrict__ r = (const ulonglong2*)&sW0[e * HID];
#pragma unroll
        for (int j = 0; j < HID / 4; j++) {
            const ulonglong2 v = r[j];
            accA[2 * j]     = ffma2(aA, v.x, accA[2 * j]);
            accA[2 * j + 1] = ffma2(aA, v.y, accA[2 * j + 1]);
            accB[2 * j]     = ffma2(aB, v.x, accB[2 * j]);
            accB[2 * j + 1] = ffma2(aB, v.y, accB[2 * j + 1]);
        }
    }

    // ReLU -> h into smem (overwrites enc region; threads touch only their own columns)
#pragma unroll
    for (int j = 0; j < HID / 2; j++) {
        float a, b; upk2(accA[j], a, b);
        sH[(2 * j) * PTS + t]     = fmaxf(a, 0.0f);
        sH[(2 * j + 1) * PTS + t] = fmaxf(b, 0.0f);
        upk2(accB[j], a, b);
        sH[(2 * j) * PTS + BLK + t]     = fmaxf(a, 0.0f);
        sH[(2 * j + 1) * PTS + BLK + t] = fmaxf(b, 0.0f);
        accA[j] = 0ull; accB[j] = 0ull;
    }

    // ================= layer 1: weight-shared across both points =================
#pragma unroll 4
    for (int i = 0; i < HID; i++) {
        const float hA = sH[i * PTS + t];
        const float hB = sH[i * PTS + BLK + t];
        const u64 aA = pk2(hA, hA), aB = pk2(hB, hB);
        const ulonglong2* __restrict__ r = (const ulonglong2*)&sW1[i * HID];
#pragma unroll
        for (int j = 0; j < HID / 4; j++) {
            const ulonglong2 v = r[j];
            accA[2 * j]     = ffma2(aA, v.x, accA[2 * j]);
            accA[2 * j + 1] = ffma2(aA, v.y, accA[2 * j + 1]);
            accB[2 * j]     = ffma2(aB, v.x, accB[2 * j]);
            accB[2 * j + 1] = ffma2(aB, v.y, accB[2 * j + 1]);
        }
    }

    // ================= ReLU + layer 2 =================
    float resA = 0.0f, resB = 0.0f;
#pragma unroll
    for (int j = 0; j < HID / 2; j++) {
        const float w0 = sW2[2 * j], w1 = sW2[2 * j + 1];
        float a, b; upk2(accA[j], a, b);
        resA = fmaf(fmaxf(a, 0.0f), w0, resA);
        resA = fmaf(fmaxf(b, 0.0f), w1, resA);
        upk2(accB[j], a, b);
        resB = fmaf(fmaxf(a, 0.0f), w0, resB);
        resB = fmaf(fmaxf(b, 0.0f), w1, resB);
    }
    if (orig0 >= 0) out[orig0] = resA;
    if (orig1 >= 0) out[orig1] = resB;
}

static LevelParams make_params(unsigned* qtotal_out) {
    LevelParams lp;
    unsigned qoff = 0;
    for (int l = 0; l < NLEV; l++) {
        const double r = floor(16.0 * pow(1.3819, (double)l));
        const int res = (int)r;
        lp.resf[l] = (float)res;
        const unsigned s1 = (unsigned)(res + 1);
        lp.s1[l] = s1;
        lp.s2[l] = s1 * s1;
        if (l < NDENSE) {
            const unsigned cnt = s1 * s1 * s1 + s1 * s1 + s1 + 2u;
            lp.qoff[l] = qoff;
            lp.qcnt[l] = cnt;
            qoff += cnt;
        }
    }
    *qtotal_out = qoff;
    return lp;
}

extern "C" void kernel_launch(void* const* d_in, const int* in_sizes, int n_in,
                              void* d_out, int out_size) {
    const float* x      = (const float*)d_in[0];
    const float* tables = (const float*)d_in[1];
    const float* W0     = (const float*)d_in[2];
    const float* W1     = (const float*)d_in[3];
    const float* W2     = (const float*)d_in[4];
    float* out = (float*)d_out;

    const int npts = out_size;
    unsigned qtotal = 0;
    LevelParams lp = make_params(&qtotal);

    static void* hist_addr = nullptr;
    if (!hist_addr) cudaGetSymbolAddress(&hist_addr, g_hist);

    const int smem_bytes = (ENC * HID + HID * HID + HID + HID * PTS) * (int)sizeof(float);
    static bool attr_set = false;
    if (!attr_set) {
        cudaFuncSetAttribute(sdf_fused, cudaFuncAttributeMaxDynamicSharedMemorySize,
                             smem_bytes);
        attr_set = true;
    }

    // ---- dense pair tables (first, so ncu -s 5 lands on sdf_fused) ----
    build_q<<<(qtotal + 255) / 256, 256>>>((const float2*)tables, lp, qtotal);

    // ---- morton counting sort (deterministic: per-point results independent
    //      of intra-bin order) ----
    cudaMemsetAsync(hist_addr, 0, NBINS * sizeof(int), 0);
    bin_points<<<(npts + 255) / 256, 256>>>(x, npts);
    scan_bins<<<1, 1024>>>();
    scatter_points<<<(npts + 255) / 256, 256>>>(x, npts);

    // ---- fused main ----
    const int grid = (npts + PTS - 1) / PTS;
    sdf_fused<<<grid, BLK, smem_bytes>>>(tables, W0, W1, W2, out, npts, lp);
}

// round 9
// speedup vs baseline: 1.2723x; 1.2723x over previous
#include <cuda_runtime.h>
#include <cmath>
#include <stdint.h>

#define NLEV   16
#define NDENSE 5
#define TSIZE  (1u << 19)
#define HID    64
#define ENC    32
#define P2     2654435761u
#define P3     805459861u
#define NMAX   1048576
#define NBINS  32768

#define BLK    128          // threads per CTA
#define PTS    256          // points per CTA (2 per thread)

typedef unsigned long long u64;

// ---- device scratch (static, no runtime allocation) ----
#define QCAP 339072
__device__ float4 g_Q[QCAP];          // dense-level x-pair tables
__device__ int    g_hist[NBINS];      // morton histogram / running offsets
__device__ float4 g_xs[NMAX];         // sorted (x01, y01, z01, orig_idx)

struct LevelParams {
    float    resf[NLEV];
    unsigned s1[NLEV];
    unsigned s2[NLEV];
    unsigned qoff[NDENSE];
    unsigned qcnt[NDENSE];
};

__device__ __forceinline__ u64 pk2(float a, float b) {
    u64 r; asm("mov.b64 %0, {%1,%2};" : "=l"(r) : "f"(a), "f"(b)); return r;
}
__device__ __forceinline__ void upk2(u64 v, float& a, float& b) {
    asm("mov.b64 {%0,%1}, %2;" : "=f"(a), "=f"(b) : "l"(v));
}
// Blackwell packed fp32 FMA (FFMA2), only reachable via PTX.
__device__ __forceinline__ u64 ffma2(u64 a, u64 b, u64 c) {
    u64 d; asm("fma.rn.f32x2 %0, %1, %2, %3;" : "=l"(d) : "l"(a), "l"(b), "l"(c)); return d;
}

// ---------- morton helpers ----------
__device__ __forceinline__ unsigned part3(unsigned v) {
    v &= 31u;
    unsigned r = 0;
#pragma unroll
    for (int b = 0; b < 5; b++) r |= ((v >> b) & 1u) << (3 * b);
    return r;
}
__device__ __forceinline__ unsigned morton_bin(float x0, float y0, float z0) {
    unsigned bx = min(31, max(0, (int)floorf(x0 * 32.0f)));
    unsigned by = min(31, max(0, (int)floorf(y0 * 32.0f)));
    unsigned bz = min(31, max(0, (int)floorf(z0 * 32.0f)));
    return part3(bx) | (part3(by) << 1) | (part3(bz) << 2);
}

// ---------- launch 1: fused morton histogram + dense pair-table build ----------
__global__ void bin_and_buildq(const float* __restrict__ x,
                               const float2* __restrict__ tables,
                               LevelParams lp, int npts, unsigned qtotal) {
    const unsigned i = blockIdx.x * blockDim.x + threadIdx.x;
    if (i < qtotal) {
        int l = 0; unsigned base = 0;
#pragma unroll
        for (int k = 0; k < NDENSE; k++) {
            unsigned o = lp.qoff[k];
            if (i >= o && i < o + lp.qcnt[k]) { l = k; base = o; }
        }
        const unsigned j = i - base;
        const float2* __restrict__ tab = tables + (size_t)l * TSIZE;
        float2 a = __ldg(&tab[j]);
        float2 b = __ldg(&tab[j + 1]);
        g_Q[i] = make_float4(a.x, a.y, b.x, b.y);
    }
    if ((int)i < npts) {
        float x0 = (x[3 * i + 0] + 1.0f) * 0.5f;
        float y0 = (x[3 * i + 1] + 1.0f) * 0.5f;
        float z0 = (x[3 * i + 2] + 1.0f) * 0.5f;
        atomicAdd(&g_hist[morton_bin(x0, y0, z0)], 1);
    }
}

// ---------- launch 2: exclusive prefix sum over NBINS ----------
__global__ void scan_bins() {
    __shared__ int warp_tot[32];
    const int t = threadIdx.x;
    const int base = t * (NBINS / 1024);
    int loc[NBINS / 1024];
    int ts = 0;
#pragma unroll
    for (int k = 0; k < NBINS / 1024; k++) { loc[k] = g_hist[base + k]; ts += loc[k]; }
    int v = ts;
    for (int d = 1; d < 32; d <<= 1) {
        int n = __shfl_up_sync(0xffffffffu, v, d);
        if ((t & 31) >= d) v += n;
    }
    if ((t & 31) == 31) warp_tot[t >> 5] = v;
    __syncthreads();
    if (t < 32) {
        int w = warp_tot[t];
        for (int d = 1; d < 32; d <<= 1) {
            int n = __shfl_up_sync(0xffffffffu, w, d);
            if (t >= d) w += n;
        }
        warp_tot[t] = w;
    }
    __syncthreads();
    int excl = v - ts + ((t >> 5) ? warp_tot[(t >> 5) - 1] : 0);
    int run = excl;
#pragma unroll
    for (int k = 0; k < NBINS / 1024; k++) { g_hist[base + k] = run; run += loc[k]; }
}

// ---------- launch 3: scatter ----------
__global__ void scatter_points(const float* __restrict__ x, int npts) {
    int p = blockIdx.x * blockDim.x + threadIdx.x;
    if (p >= npts) return;
    float x0 = (x[3 * p + 0] + 1.0f) * 0.5f;
    float y0 = (x[3 * p + 1] + 1.0f) * 0.5f;
    float z0 = (x[3 * p + 2] + 1.0f) * 0.5f;
    int pos = atomicAdd(&g_hist[morton_bin(x0, y0, z0)], 1);
    g_xs[pos] = make_float4(x0, y0, z0, __int_as_float(p));
}

// ---------- per-level corner fetch: issue loads, return feature pairs ----------
struct Frac { float fx, fy, fz; };

// ---------- launch 4: main fused kernel (128 thr, 256 pts, interleaved ILP) ----------
__global__ void __launch_bounds__(BLK) sdf_fused(
    const float* __restrict__ tables,
    const float* __restrict__ W0,
    const float* __restrict__ W1,
    const float* __restrict__ W2,
    float* __restrict__ out,
    int npts, LevelParams lp)
{
    extern __shared__ __align__(16) float smem[];
    float* sW0 = smem;                       // 2048 floats
    float* sW1 = sW0 + ENC * HID;            // 4096
    float* sW2 = sW1 + HID * HID;            // 64
    float* sH  = sW2 + HID;                  // 64*PTS

    {
        int t = threadIdx.x;
        float4*       s0 = (float4*)sW0;  const float4* g0 = (const float4*)W0;
        for (int i = t; i < ENC * HID / 4; i += BLK) s0[i] = g0[i];
        float4*       s1 = (float4*)sW1;  const float4* g1 = (const float4*)W1;
        for (int i = t; i < HID * HID / 4; i += BLK) s1[i] = g1[i];
        if (t < HID / 4) ((float4*)sW2)[t] = ((const float4*)W2)[t];
    }
    __syncthreads();

    const int t = threadIdx.x;
    const int base = blockIdx.x * PTS;
    const int ptA = base + t;
    const int ptB = base + BLK + t;
    const bool vA = ptA < npts, vB = ptB < npts;

    const float4 xsA = g_xs[vA ? ptA : 0];
    const float4 xsB = g_xs[vB ? ptB : 0];
    const int origA = vA ? __float_as_int(xsA.w) : -1;
    const int origB = vB ? __float_as_int(xsB.w) : -1;
    const float xA = xsA.x, yA = xsA.y, zA = xsA.z;
    const float xB = xsB.x, yB = xsB.y, zB = xsB.z;

    // ================= gather phase: A and B interleaved per level =================
    // ---- dense levels ----
#pragma unroll
    for (int l = 0; l < NDENSE; l++) {
        const float rf = lp.resf[l];
        const unsigned s1 = lp.s1[l], s2 = lp.s2[l];
        const float4* __restrict__ Q = g_Q + lp.qoff[l];

        // point A indices
        const float pxA = xA * rf, pyA = yA * rf, pzA = zA * rf;
        const float fpxA = floorf(pxA), fpyA = floorf(pyA), fpzA = floorf(pzA);
        const float fxA = pxA - fpxA, fyA = pyA - fpyA, fzA = pzA - fpzA;
        const unsigned bA0 = (unsigned)fpxA + (unsigned)fpyA * s1 + (unsigned)fpzA * s2;
        // point B indices
        const float pxB = xB * rf, pyB = yB * rf, pzB = zB * rf;
        const float fpxB = floorf(pxB), fpyB = floorf(pyB), fpzB = floorf(pzB);
        const float fxB = pxB - fpxB, fyB = pyB - fpyB, fzB = pzB - fpzB;
        const unsigned bB0 = (unsigned)fpxB + (unsigned)fpyB * s1 + (unsigned)fpzB * s2;

        const unsigned bbA[4] = {bA0, bA0 + s2, bA0 + s1, bA0 + s1 + s2};
        const unsigned bbB[4] = {bB0, bB0 + s2, bB0 + s1, bB0 + s1 + s2};

        // issue all 8 loads before consuming
        float4 qA[4], qB[4];
#pragma unroll
        for (int j = 0; j < 4; j++) qA[j] = __ldg(&Q[bbA[j]]);
#pragma unroll
        for (int j = 0; j < 4; j++) qB[j] = __ldg(&Q[bbB[j]]);

        {
            const float gx = 1.0f - fxA, gy = 1.0f - fyA, gz = 1.0f - fzA;
            const float wyz[4] = {gy * gz, gy * fzA, fyA * gz, fyA * fzA};
            float e0 = 0.0f, e1 = 0.0f;
#pragma unroll
            for (int j = 0; j < 4; j++) {
                const float w0 = wyz[j] * gx, w1 = wyz[j] * fxA;
                e0 = fmaf(w0, qA[j].x, fmaf(w1, qA[j].z, e0));
                e1 = fmaf(w0, qA[j].y, fmaf(w1, qA[j].w, e1));
            }
            sH[(2 * l) * PTS + t] = e0;
            sH[(2 * l + 1) * PTS + t] = e1;
        }
        {
            const float gx = 1.0f - fxB, gy = 1.0f - fyB, gz = 1.0f - fzB;
            const float wyz[4] = {gy * gz, gy * fzB, fyB * gz, fyB * fzB};
            float e0 = 0.0f, e1 = 0.0f;
#pragma unroll
            for (int j = 0; j < 4; j++) {
                const float w0 = wyz[j] * gx, w1 = wyz[j] * fxB;
                e0 = fmaf(w0, qB[j].x, fmaf(w1, qB[j].z, e0));
                e1 = fmaf(w0, qB[j].y, fmaf(w1, qB[j].w, e1));
            }
            sH[(2 * l) * PTS + BLK + t] = e0;
            sH[(2 * l + 1) * PTS + BLK + t] = e1;
        }
    }

    // ---- hashed levels ----
#pragma unroll 1
    for (int l = NDENSE; l < NLEV; l++) {
        const float rf = lp.resf[l];
        const float2* __restrict__ tab2 = ((const float2*)tables) + (size_t)l * TSIZE;
        const float4* __restrict__ tab4 = (const float4*)tab2;
        const unsigned m = TSIZE - 1u;

        // --- point A: compute + issue loads ---
        const float pxA = xA * rf, pyA = yA * rf, pzA = zA * rf;
        const float fpxA = floorf(pxA), fpyA = floorf(pyA), fpzA = floorf(pzA);
        const float fxA = pxA - fpxA, fyA = pyA - fpyA, fzA = pzA - fpzA;
        const unsigned cxA = (unsigned)fpxA;
        const unsigned ayA = (unsigned)fpyA * P2, azA = (unsigned)fpzA * P3;
        const unsigned sA[4] = {ayA ^ azA, ayA ^ (azA + P3),
                                (ayA + P2) ^ azA, (ayA + P2) ^ (azA + P3)};
        float2 fA0[4], fA1[4];
        if ((cxA & 1u) == 0u) {
#pragma unroll
            for (int j = 0; j < 4; j++) {
                const unsigned i0 = (cxA ^ sA[j]) & m;
                const float4 q = __ldg(&tab4[i0 >> 1]);
                const bool hi = (i0 & 1u) != 0u;
                fA0[j] = hi ? make_float2(q.z, q.w) : make_float2(q.x, q.y);
                fA1[j] = hi ? make_float2(q.x, q.y) : make_float2(q.z, q.w);
            }
        } else {
            const unsigned cx1 = cxA + 1u;
#pragma unroll
            for (int j = 0; j < 4; j++) {
                fA0[j] = __ldg(&tab2[(cxA ^ sA[j]) & m]);
                fA1[j] = __ldg(&tab2[(cx1 ^ sA[j]) & m]);
            }
        }

        // --- point B: compute + issue loads (overlaps A's in-flight loads) ---
        const float pxB = xB * rf, pyB = yB * rf, pzB = zB * rf;
        const float fpxB = floorf(pxB), fpyB = floorf(pyB), fpzB = floorf(pzB);
        const float fxB = pxB - fpxB, fyB = pyB - fpyB, fzB = pzB - fpzB;
        const unsigned cxB = (unsigned)fpxB;
        const unsigned ayB = (unsigned)fpyB * P2, azB = (unsigned)fpzB * P3;
        const unsigned sB[4] = {ayB ^ azB, ayB ^ (azB + P3),
                                (ayB + P2) ^ azB, (ayB + P2) ^ (azB + P3)};
        float2 fB0[4], fB1[4];
        if ((cxB & 1u) == 0u) {
#pragma unroll
            for (int j = 0; j < 4; j++) {
                const unsigned i0 = (cxB ^ sB[j]) & m;
                const float4 q = __ldg(&tab4[i0 >> 1]);
                const bool hi = (i0 & 1u) != 0u;
                fB0[j] = hi ? make_float2(q.z, q.w) : make_float2(q.x, q.y);
                fB1[j] = hi ? make_float2(q.x, q.y) : make_float2(q.z, q.w);
            }
        } else {
            const unsigned cx1 = cxB + 1u;
#pragma unroll
            for (int j = 0; j < 4; j++) {
                fB0[j] = __ldg(&tab2[(cxB ^ sB[j]) & m]);
                fB1[j] = __ldg(&tab2[(cx1 ^ sB[j]) & m]);
            }
        }

        // --- consume A ---
        {
            const float gx = 1.0f - fxA, gy = 1.0f - fyA, gz = 1.0f - fzA;
            const float wyz[4] = {gy * gz, gy * fzA, fyA * gz, fyA * fzA};
            float e0 = 0.0f, e1 = 0.0f;
#pragma unroll
            for (int j = 0; j < 4; j++) {
                const float w0 = wyz[j] * gx, w1 = wyz[j] * fxA;
                e0 = fmaf(w0, fA0[j].x, fmaf(w1, fA1[j].x, e0));
                e1 = fmaf(w0, fA0[j].y, fmaf(w1, fA1[j].y, e1));
            }
            sH[(2 * l) * PTS + t] = e0;
            sH[(2 * l + 1) * PTS + t] = e1;
        }
        // --- consume B ---
        {
            const float gx = 1.0f - fxB, gy = 1.0f - fyB, gz = 1.0f - fzB;
            const float wyz[4] = {gy * gz, gy * fzB, fyB * gz, fyB * fzB};
            float e0 = 0.0f, e1 = 0.0f;
#pragma unroll
            for (int j = 0; j < 4; j++) {
                const float w0 = wyz[j] * gx, w1 = wyz[j] * fxB;
                e0 = fmaf(w0, fB0[j].x, fmaf(w1, fB1[j].x, e0));
                e1 = fmaf(w0, fB0[j].y, fmaf(w1, fB1[j].y, e1));
            }
            sH[(2 * l) * PTS + BLK + t] = e0;
            sH[(2 * l + 1) * PTS + BLK + t] = e1;
        }
    }

    // ================= layer 0: weight-shared across both points =================
    u64 accA[HID / 2], accB[HID / 2];
#pragma unroll
    for (int j = 0; j < HID / 2; j++) { accA[j] = 0ull; accB[j] = 0ull; }

#pragma unroll 2
    for (int e = 0; e < ENC; e++) {
        const float hA = sH[e * PTS + t];
        const float hB = sH[e * PTS + BLK + t];
        const u64 aA = pk2(hA, hA), aB = pk2(hB, hB);
        const ulonglong2* __restrict__ r = (const ulonglong2*)&sW0[e * HID];
#pragma unroll
        for (int j = 0; j < HID / 4; j++) {
            const ulonglong2 v = r[j];
            accA[2 * j]     = ffma2(aA, v.x, accA[2 * j]);
            accA[2 * j + 1] = ffma2(aA, v.y, accA[2 * j + 1]);
            accB[2 * j]     = ffma2(aB, v.x, accB[2 * j]);
            accB[2 * j + 1] = ffma2(aB, v.y, accB[2 * j + 1]);
        }
    }

    // ReLU -> h into smem (threads touch only their own columns)
#pragma unroll
    for (int j = 0; j < HID / 2; j++) {
        float a, b; upk2(accA[j], a, b);
        sH[(2 * j) * PTS + t]     = fmaxf(a, 0.0f);
        sH[(2 * j + 1) * PTS + t] = fmaxf(b, 0.0f);
        upk2(accB[j], a, b);
        sH[(2 * j) * PTS + BLK + t]     = fmaxf(a, 0.0f);
        sH[(2 * j + 1) * PTS + BLK + t] = fmaxf(b, 0.0f);
        accA[j] = 0ull; accB[j] = 0ull;
    }

    // ================= layer 1: weight-shared across both points =================
#pragma unroll 4
    for (int i = 0; i < HID; i++) {
        const float hA = sH[i * PTS + t];
        const float hB = sH[i * PTS + BLK + t];
        const u64 aA = pk2(hA, hA), aB = pk2(hB, hB);
        const ulonglong2* __restrict__ r = (const ulonglong2*)&sW1[i * HID];
#pragma unroll
        for (int j = 0; j < HID / 4; j++) {
            const ulonglong2 v = r[j];
            accA[2 * j]     = ffma2(aA, v.x, accA[2 * j]);
            accA[2 * j + 1] = ffma2(aA, v.y, accA[2 * j + 1]);
            accB[2 * j]     = ffma2(aB, v.x, accB[2 * j]);
            accB[2 * j + 1] = ffma2(aB, v.y, accB[2 * j + 1]);
        }
    }

    // ================= ReLU + layer 2 =================
    float resA = 0.0f, resB = 0.0f;
#pragma unroll
    for (int j = 0; j < HID / 2; j++) {
        const float w0 = sW2[2 * j], w1 = sW2[2 * j + 1];
        float a, b; upk2(accA[j], a, b);
        resA = fmaf(fmaxf(a, 0.0f), w0, resA);
        resA = fmaf(fmaxf(b, 0.0f), w1, resA);
        upk2(accB[j], a, b);
        resB = fmaf(fmaxf(a, 0.0f), w0, resB);
        resB = fmaf(fmaxf(b, 0.0f), w1, resB);
    }
    if (origA >= 0) out[origA] = resA;
    if (origB >= 0) out[origB] = resB;
}

static LevelParams make_params(unsigned* qtotal_out) {
    LevelParams lp;
    unsigned qoff = 0;
    for (int l = 0; l < NLEV; l++) {
        const double r = floor(16.0 * pow(1.3819, (double)l));
        const int res = (int)r;
        lp.resf[l] = (float)res;
        const unsigned s1 = (unsigned)(res + 1);
        lp.s1[l] = s1;
        lp.s2[l] = s1 * s1;
        if (l < NDENSE) {
            const unsigned cnt = s1 * s1 * s1 + s1 * s1 + s1 + 2u;
            lp.qoff[l] = qoff;
            lp.qcnt[l] = cnt;
            qoff += cnt;
        }
    }
    *qtotal_out = qoff;
    return lp;
}

extern "C" void kernel_launch(void* const* d_in, const int* in_sizes, int n_in,
                              void* d_out, int out_size) {
    const float* x      = (const float*)d_in[0];
    const float* tables = (const float*)d_in[1];
    const float* W0     = (const float*)d_in[2];
    const float* W1     = (const float*)d_in[3];
    const float* W2     = (const float*)d_in[4];
    float* out = (float*)d_out;

    const int npts = out_size;
    unsigned qtotal = 0;
    LevelParams lp = make_params(&qtotal);

    static void* hist_addr = nullptr;
    if (!hist_addr) cudaGetSymbolAddress(&hist_addr, g_hist);

    const int smem_bytes = (ENC * HID + HID * HID + HID + HID * PTS) * (int)sizeof(float);
    static bool attr_set = false;
    if (!attr_set) {
        cudaFuncSetAttribute(sdf_fused, cudaFuncAttributeMaxDynamicSharedMemorySize,
                             smem_bytes);
        attr_set = true;
    }

    // memset is not a counted kernel launch; keeps sdf_fused at launch #4 for ncu
    cudaMemsetAsync(hist_addr, 0, NBINS * sizeof(int), 0);

    // 1: fused morton histogram + dense pair tables
    {
        const unsigned total = (unsigned)npts > qtotal ? (unsigned)npts : qtotal;
        bin_and_buildq<<<(total + 255) / 256, 256>>>(x, (const float2*)tables, lp,
                                                     npts, qtotal);
    }
    // 2: prefix sum
    scan_bins<<<1, 1024>>>();
    // 3: scatter (deterministic output: per-point results independent of
    //    intra-bin order)
    scatter_points<<<(npts + 255) / 256, 256>>>(x, npts);
    // 4: fused main
    const int grid = (npts + PTS - 1) / PTS;
    sdf_fused<<<grid, BLK, smem_bytes>>>(tables, W0, W1, W2, out, npts, lp);
}

// round 10
// speedup vs baseline: 1.2988x; 1.0208x over previous
#include <cuda_runtime.h>
#include <cmath>
#include <stdint.h>

#define NLEV   16
#define NDENSE 5
#define TSIZE  (1u << 19)
#define HID    64
#define ENC    32
#define P2     2654435761u
#define P3     805459861u
#define NMAX   1048576
#define NBINS  32768

#define BLK    128          // threads per CTA
#define PTS    256          // points per CTA (2 per thread)

typedef unsigned long long u64;

// ---- device scratch (static, no runtime allocation) ----
#define QCAP 339072
__device__ float4 g_Q[QCAP];          // dense-level x-pair tables
__device__ int    g_hist[NBINS];      // morton histogram / running offsets
__device__ float4 g_xs[NMAX];         // sorted (x01, y01, z01, orig_idx)

struct LevelParams {
    float    resf[NLEV];
    unsigned s1[NLEV];
    unsigned s2[NLEV];
    unsigned qoff[NDENSE];
    unsigned qcnt[NDENSE];
};

__device__ __forceinline__ u64 pk2(float a, float b) {
    u64 r; asm("mov.b64 %0, {%1,%2};" : "=l"(r) : "f"(a), "f"(b)); return r;
}
__device__ __forceinline__ void upk2(u64 v, float& a, float& b) {
    asm("mov.b64 {%0,%1}, %2;" : "=f"(a), "=f"(b) : "l"(v));
}
// Blackwell packed fp32 FMA (FFMA2), only reachable via PTX.
__device__ __forceinline__ u64 ffma2(u64 a, u64 b, u64 c) {
    u64 d; asm("fma.rn.f32x2 %0, %1, %2, %3;" : "=l"(d) : "l"(a), "l"(b), "l"(c)); return d;
}

// ---------- morton helpers ----------
__device__ __forceinline__ unsigned part3(unsigned v) {
    v &= 31u;
    unsigned r = 0;
#pragma unroll
    for (int b = 0; b < 5; b++) r |= ((v >> b) & 1u) << (3 * b);
    return r;
}
__device__ __forceinline__ unsigned morton_bin(float x0, float y0, float z0) {
    unsigned bx = min(31, max(0, (int)floorf(x0 * 32.0f)));
    unsigned by = min(31, max(0, (int)floorf(y0 * 32.0f)));
    unsigned bz = min(31, max(0, (int)floorf(z0 * 32.0f)));
    return part3(bx) | (part3(by) << 1) | (part3(bz) << 2);
}

// ---------- launch 1: fused morton histogram + dense pair-table build ----------
__global__ void bin_and_buildq(const float* __restrict__ x,
                               const float2* __restrict__ tables,
                               LevelParams lp, int npts, unsigned qtotal) {
    const unsigned i = blockIdx.x * blockDim.x + threadIdx.x;
    if (i < qtotal) {
        int l = 0; unsigned base = 0;
#pragma unroll
        for (int k = 0; k < NDENSE; k++) {
            unsigned o = lp.qoff[k];
            if (i >= o && i < o + lp.qcnt[k]) { l = k; base = o; }
        }
        const unsigned j = i - base;
        const float2* __restrict__ tab = tables + (size_t)l * TSIZE;
        float2 a = __ldg(&tab[j]);
        float2 b = __ldg(&tab[j + 1]);
        g_Q[i] = make_float4(a.x, a.y, b.x, b.y);
    }
    if ((int)i < npts) {
        float x0 = (x[3 * i + 0] + 1.0f) * 0.5f;
        float y0 = (x[3 * i + 1] + 1.0f) * 0.5f;
        float z0 = (x[3 * i + 2] + 1.0f) * 0.5f;
        atomicAdd(&g_hist[morton_bin(x0, y0, z0)], 1);
    }
}

// ---------- launch 2: exclusive prefix sum over NBINS ----------
__global__ void scan_bins() {
    __shared__ int warp_tot[32];
    const int t = threadIdx.x;
    const int base = t * (NBINS / 1024);
    int loc[NBINS / 1024];
    int ts = 0;
#pragma unroll
    for (int k = 0; k < NBINS / 1024; k++) { loc[k] = g_hist[base + k]; ts += loc[k]; }
    int v = ts;
    for (int d = 1; d < 32; d <<= 1) {
        int n = __shfl_up_sync(0xffffffffu, v, d);
        if ((t & 31) >= d) v += n;
    }
    if ((t & 31) == 31) warp_tot[t >> 5] = v;
    __syncthreads();
    if (t < 32) {
        int w = warp_tot[t];
        for (int d = 1; d < 32; d <<= 1) {
            int n = __shfl_up_sync(0xffffffffu, w, d);
            if (t >= d) w += n;
        }
        warp_tot[t] = w;
    }
    __syncthreads();
    int excl = v - ts + ((t >> 5) ? warp_tot[(t >> 5) - 1] : 0);
    int run = excl;
#pragma unroll
    for (int k = 0; k < NBINS / 1024; k++) { g_hist[base + k] = run; run += loc[k]; }
}

// ---------- launch 3: scatter ----------
__global__ void scatter_points(const float* __restrict__ x, int npts) {
    int p = blockIdx.x * blockDim.x + threadIdx.x;
    if (p >= npts) return;
    float x0 = (x[3 * p + 0] + 1.0f) * 0.5f;
    float y0 = (x[3 * p + 1] + 1.0f) * 0.5f;
    float z0 = (x[3 * p + 2] + 1.0f) * 0.5f;
    int pos = atomicAdd(&g_hist[morton_bin(x0, y0, z0)], 1);
    g_xs[pos] = make_float4(x0, y0, z0, __int_as_float(p));
}

// ---------- hashed-level issue/consume split (loads in flight across levels) ----------
// Issue: compute indices, fire loads, stash RAW float4s + sel bits. No use of
// loaded data here, so the warp does not block.
__device__ __forceinline__ void hashed_issue(
    float x0, float y0, float z0, float rf,
    const float2* __restrict__ tab2, const float4* __restrict__ tab4, unsigned m,
    float& fx, float& fy, float& fz, float4 q[4], unsigned& sel)
{
    const float px = x0 * rf, py = y0 * rf, pz = z0 * rf;
    const float fpx = floorf(px), fpy = floorf(py), fpz = floorf(pz);
    fx = px - fpx; fy = py - fpy; fz = pz - fpz;
    const unsigned cx = (unsigned)fpx;
    const unsigned ay = (unsigned)fpy * P2, az = (unsigned)fpz * P3;
    const unsigned s[4] = {ay ^ az, ay ^ (az + P3),
                           (ay + P2) ^ az, (ay + P2) ^ (az + P3)};
    sel = 0u;
    if ((cx & 1u) == 0u) {
#pragma unroll
        for (int j = 0; j < 4; j++) {
            const unsigned i0 = (cx ^ s[j]) & m;
            q[j] = __ldg(&tab4[i0 >> 1]);
            sel |= (i0 & 1u) << j;
        }
    } else {
        const unsigned cx1 = cx + 1u;
#pragma unroll
        for (int j = 0; j < 4; j++) {
            const float2 a = __ldg(&tab2[(cx ^ s[j]) & m]);
            const float2 b = __ldg(&tab2[(cx1 ^ s[j]) & m]);
            q[j] = make_float4(a.x, a.y, b.x, b.y);   // register naming only
        }
    }
}

// Consume: hi/lo selects happen HERE (first true use of the loaded data).
__device__ __forceinline__ void hashed_consume(
    float fx, float fy, float fz, const float4 q[4], unsigned sel,
    float* __restrict__ d0, float* __restrict__ d1)
{
    const float gx = 1.0f - fx, gy = 1.0f - fy, gz = 1.0f - fz;
    const float wyz[4] = {gy * gz, gy * fz, fy * gz, fy * fz};
    float e0 = 0.0f, e1 = 0.0f;
#pragma unroll
    for (int j = 0; j < 4; j++) {
        const bool hi = (sel >> j) & 1u;
        const float a0 = hi ? q[j].z : q[j].x;
        const float a1 = hi ? q[j].w : q[j].y;
        const float b0 = hi ? q[j].x : q[j].z;
        const float b1 = hi ? q[j].y : q[j].w;
        const float w0 = wyz[j] * gx, w1 = wyz[j] * fx;
        e0 = fmaf(w0, a0, fmaf(w1, b0, e0));
        e1 = fmaf(w0, a1, fmaf(w1, b1, e1));
    }
    *d0 = e0;
    *d1 = e1;
}

// ---------- launch 4: main fused kernel ----------
__global__ void __launch_bounds__(BLK) sdf_fused(
    const float* __restrict__ tables,
    const float* __restrict__ W0,
    const float* __restrict__ W1,
    const float* __restrict__ W2,
    float* __restrict__ out,
    int npts, LevelParams lp)
{
    extern __shared__ __align__(16) float smem[];
    float* sW0 = smem;                       // 2048 floats
    float* sW1 = sW0 + ENC * HID;            // 4096
    float* sW2 = sW1 + HID * HID;            // 64
    float* sH  = sW2 + HID;                  // 64*PTS

    {
        int t = threadIdx.x;
        float4*       s0 = (float4*)sW0;  const float4* g0 = (const float4*)W0;
        for (int i = t; i < ENC * HID / 4; i += BLK) s0[i] = g0[i];
        float4*       s1 = (float4*)sW1;  const float4* g1 = (const float4*)W1;
        for (int i = t; i < HID * HID / 4; i += BLK) s1[i] = g1[i];
        if (t < HID / 4) ((float4*)sW2)[t] = ((const float4*)W2)[t];
    }
    __syncthreads();

    const int t = threadIdx.x;
    const int base = blockIdx.x * PTS;
    const int ptA = base + t;
    const int ptB = base + BLK + t;
    const bool vA = ptA < npts, vB = ptB < npts;

    const float4 xsA = g_xs[vA ? ptA : 0];
    const float4 xsB = g_xs[vB ? ptB : 0];
    const int origA = vA ? __float_as_int(xsA.w) : -1;
    const int origB = vB ? __float_as_int(xsB.w) : -1;
    const float xA = xsA.x, yA = xsA.y, zA = xsA.z;
    const float xB = xsB.x, yB = xsB.y, zB = xsB.z;

    // ================= dense levels: A+B interleaved per level =================
#pragma unroll
    for (int l = 0; l < NDENSE; l++) {
        const float rf = lp.resf[l];
        const unsigned s1 = lp.s1[l], s2 = lp.s2[l];
        const float4* __restrict__ Q = g_Q + lp.qoff[l];

        const float pxA = xA * rf, pyA = yA * rf, pzA = zA * rf;
        const float fpxA = floorf(pxA), fpyA = floorf(pyA), fpzA = floorf(pzA);
        const float fxA = pxA - fpxA, fyA = pyA - fpyA, fzA = pzA - fpzA;
        const unsigned bA0 = (unsigned)fpxA + (unsigned)fpyA * s1 + (unsigned)fpzA * s2;
        const float pxB = xB * rf, pyB = yB * rf, pzB = zB * rf;
        const float fpxB = floorf(pxB), fpyB = floorf(pyB), fpzB = floorf(pzB);
        const float fxB = pxB - fpxB, fyB = pyB - fpyB, fzB = pzB - fpzB;
        const unsigned bB0 = (unsigned)fpxB + (unsigned)fpyB * s1 + (unsigned)fpzB * s2;

        const unsigned bbA[4] = {bA0, bA0 + s2, bA0 + s1, bA0 + s1 + s2};
        const unsigned bbB[4] = {bB0, bB0 + s2, bB0 + s1, bB0 + s1 + s2};

        float4 qA[4], qB[4];
#pragma unroll
        for (int j = 0; j < 4; j++) qA[j] = __ldg(&Q[bbA[j]]);
#pragma unroll
        for (int j = 0; j < 4; j++) qB[j] = __ldg(&Q[bbB[j]]);

        {
            const float gx = 1.0f - fxA, gy = 1.0f - fyA, gz = 1.0f - fzA;
            const float wyz[4] = {gy * gz, gy * fzA, fyA * gz, fyA * fzA};
            float e0 = 0.0f, e1 = 0.0f;
#pragma unroll
            for (int j = 0; j < 4; j++) {
                const float w0 = wyz[j] * gx, w1 = wyz[j] * fxA;
                e0 = fmaf(w0, qA[j].x, fmaf(w1, qA[j].z, e0));
                e1 = fmaf(w0, qA[j].y, fmaf(w1, qA[j].w, e1));
            }
            sH[(2 * l) * PTS + t] = e0;
            sH[(2 * l + 1) * PTS + t] = e1;
        }
        {
            const float gx = 1.0f - fxB, gy = 1.0f - fyB, gz = 1.0f - fzB;
            const float wyz[4] = {gy * gz, gy * fzB, fyB * gz, fyB * fzB};
            float e0 = 0.0f, e1 = 0.0f;
#pragma unroll
            for (int j = 0; j < 4; j++) {
                const float w0 = wyz[j] * gx, w1 = wyz[j] * fxB;
                e0 = fmaf(w0, qB[j].x, fmaf(w1, qB[j].z, e0));
                e1 = fmaf(w0, qB[j].y, fmaf(w1, qB[j].w, e1));
            }
            sH[(2 * l) * PTS + BLK + t] = e0;
            sH[(2 * l + 1) * PTS + BLK + t] = e1;
        }
    }

    // ================= hashed levels: processed in PAIRS (16 loads in flight) ======
    {
        const unsigned m = TSIZE - 1u;
#pragma unroll 1
        for (int l = NDENSE; l + 1 < NLEV; l += 2) {
            const float rf0 = lp.resf[l], rf1 = lp.resf[l + 1];
            const float2* __restrict__ t2a = ((const float2*)tables) + (size_t)l * TSIZE;
            const float4* __restrict__ t4a = (const float4*)t2a;
            const float2* __restrict__ t2b = t2a + TSIZE;
            const float4* __restrict__ t4b = (const float4*)t2b;

            float fxA0, fyA0, fzA0, fxB0, fyB0, fzB0;
            float fxA1, fyA1, fzA1, fxB1, fyB1, fzB1;
            float4 qA0[4], qB0[4], qA1[4], qB1[4];
            unsigned sA0, sB0, sA1, sB1;

            hashed_issue(xA, yA, zA, rf0, t2a, t4a, m, fxA0, fyA0, fzA0, qA0, sA0);
            hashed_issue(xB, yB, zB, rf0, t2a, t4a, m, fxB0, fyB0, fzB0, qB0, sB0);
            hashed_issue(xA, yA, zA, rf1, t2b, t4b, m, fxA1, fyA1, fzA1, qA1, sA1);
            hashed_issue(xB, yB, zB, rf1, t2b, t4b, m, fxB1, fyB1, fzB1, qB1, sB1);

            hashed_consume(fxA0, fyA0, fzA0, qA0, sA0,
                           &sH[(2 * l) * PTS + t],           &sH[(2 * l + 1) * PTS + t]);
            hashed_consume(fxB0, fyB0, fzB0, qB0, sB0,
                           &sH[(2 * l) * PTS + BLK + t],     &sH[(2 * l + 1) * PTS + BLK + t]);
            hashed_consume(fxA1, fyA1, fzA1, qA1, sA1,
                           &sH[(2 * l + 2) * PTS + t],       &sH[(2 * l + 3) * PTS + t]);
            hashed_consume(fxB1, fyB1, fzB1, qB1, sB1,
                           &sH[(2 * l + 2) * PTS + BLK + t], &sH[(2 * l + 3) * PTS + BLK + t]);
        }
        // last (odd) level 15
        {
            const int l = NLEV - 1;
            const float rf = lp.resf[l];
            const float2* __restrict__ t2 = ((const float2*)tables) + (size_t)l * TSIZE;
            const float4* __restrict__ t4 = (const float4*)t2;
            float fxA0, fyA0, fzA0, fxB0, fyB0, fzB0;
            float4 qA0[4], qB0[4];
            unsigned sA0, sB0;
            hashed_issue(xA, yA, zA, rf, t2, t4, m, fxA0, fyA0, fzA0, qA0, sA0);
            hashed_issue(xB, yB, zB, rf, t2, t4, m, fxB0, fyB0, fzB0, qB0, sB0);
            hashed_consume(fxA0, fyA0, fzA0, qA0, sA0,
                           &sH[(2 * l) * PTS + t],       &sH[(2 * l + 1) * PTS + t]);
            hashed_consume(fxB0, fyB0, fzB0, qB0, sB0,
                           &sH[(2 * l) * PTS + BLK + t], &sH[(2 * l + 1) * PTS + BLK + t]);
        }
    }

    // ================= layer 0: weight-shared across both points =================
    u64 accA[HID / 2], accB[HID / 2];
#pragma unroll
    for (int j = 0; j < HID / 2; j++) { accA[j] = 0ull; accB[j] = 0ull; }

#pragma unroll 2
    for (int e = 0; e < ENC; e++) {
        const float hA = sH[e * PTS + t];
        const float hB = sH[e * PTS + BLK + t];
        const u64 aA = pk2(hA, hA), aB = pk2(hB, hB);
        const ulonglong2* __restrict__ r = (const ulonglong2*)&sW0[e * HID];
#pragma unroll
        for (int j = 0; j < HID / 4; j++) {
            const ulonglong2 v = r[j];
            accA[2 * j]     = ffma2(aA, v.x, accA[2 * j]);
            accA[2 * j + 1] = ffma2(aA, v.y, accA[2 * j + 1]);
            accB[2 * j]     = ffma2(aB, v.x, accB[2 * j]);
            accB[2 * j + 1] = ffma2(aB, v.y, accB[2 * j + 1]);
        }
    }

    // ReLU -> h into smem (threads touch only their own columns)
#pragma unroll
    for (int j = 0; j < HID / 2; j++) {
        float a, b; upk2(accA[j], a, b);
        sH[(2 * j) * PTS + t]     = fmaxf(a, 0.0f);
        sH[(2 * j + 1) * PTS + t] = fmaxf(b, 0.0f);
        upk2(accB[j], a, b);
        sH[(2 * j) * PTS + BLK + t]     = fmaxf(a, 0.0f);
        sH[(2 * j + 1) * PTS + BLK + t] = fmaxf(b, 0.0f);
        accA[j] = 0ull; accB[j] = 0ull;
    }

    // ================= layer 1: weight-shared across both points =================
#pragma unroll 4
    for (int i = 0; i < HID; i++) {
        const float hA = sH[i * PTS + t];
        const float hB = sH[i * PTS + BLK + t];
        const u64 aA = pk2(hA, hA), aB = pk2(hB, hB);
        const ulonglong2* __restrict__ r = (const ulonglong2*)&sW1[i * HID];
#pragma unroll
        for (int j = 0; j < HID / 4; j++) {
            const ulonglong2 v = r[j];
            accA[2 * j]     = ffma2(aA, v.x, accA[2 * j]);
            accA[2 * j + 1] = ffma2(aA, v.y, accA[2 * j + 1]);
            accB[2 * j]     = ffma2(aB, v.x, accB[2 * j]);
            accB[2 * j + 1] = ffma2(aB, v.y, accB[2 * j + 1]);
        }
    }

    // ================= ReLU + layer 2 =================
    float resA = 0.0f, resB = 0.0f;
#pragma unroll
    for (int j = 0; j < HID / 2; j++) {
        const float w0 = sW2[2 * j], w1 = sW2[2 * j + 1];
        float a, b; upk2(accA[j], a, b);
        resA = fmaf(fmaxf(a, 0.0f), w0, resA);
        resA = fmaf(fmaxf(b, 0.0f), w1, resA);
        upk2(accB[j], a, b);
        resB = fmaf(fmaxf(a, 0.0f), w0, resB);
        resB = fmaf(fmaxf(b, 0.0f), w1, resB);
    }
    if (origA >= 0) out[origA] = resA;
    if (origB >= 0) out[origB] = resB;
}

static LevelParams make_params(unsigned* qtotal_out) {
    LevelParams lp;
    unsigned qoff = 0;
    for (int l = 0; l < NLEV; l++) {
        const double r = floor(16.0 * pow(1.3819, (double)l));
        const int res = (int)r;
        lp.resf[l] = (float)res;
        const unsigned s1 = (unsigned)(res + 1);
        lp.s1[l] = s1;
        lp.s2[l] = s1 * s1;
        if (l < NDENSE) {
            const unsigned cnt = s1 * s1 * s1 + s1 * s1 + s1 + 2u;
            lp.qoff[l] = qoff;
            lp.qcnt[l] = cnt;
            qoff += cnt;
        }
    }
    *qtotal_out = qoff;
    return lp;
}

extern "C" void kernel_launch(void* const* d_in, const int* in_sizes, int n_in,
                              void* d_out, int out_size) {
    const float* x      = (const float*)d_in[0];
    const float* tables = (const float*)d_in[1];
    const float* W0     = (const float*)d_in[2];
    const float* W1     = (const float*)d_in[3];
    const float* W2     = (const float*)d_in[4];
    float* out = (float*)d_out;

    const int npts = out_size;
    unsigned qtotal = 0;
    LevelParams lp = make_params(&qtotal);

    static void* hist_addr = nullptr;
    if (!hist_addr) cudaGetSymbolAddress(&hist_addr, g_hist);

    const int smem_bytes = (ENC * HID + HID * HID + HID + HID * PTS) * (int)sizeof(float);
    static bool attr_set = false;
    if (!attr_set) {
        cudaFuncSetAttribute(sdf_fused, cudaFuncAttributeMaxDynamicSharedMemorySize,
                             smem_bytes);
        attr_set = true;
    }

    cudaMemsetAsync(hist_addr, 0, NBINS * sizeof(int), 0);

    // 1: fused morton histogram + dense pair tables
    {
        const unsigned total = (unsigned)npts > qtotal ? (unsigned)npts : qtotal;
        bin_and_buildq<<<(total + 255) / 256, 256>>>(x, (const float2*)tables, lp,
                                                     npts, qtotal);
    }
    // 2: prefix sum
    scan_bins<<<1, 1024>>>();
    // 3: scatter (deterministic output: per-point results independent of
    //    intra-bin order)
    scatter_points<<<(npts + 255) / 256, 256>>>(x, npts);
    // 4: fused main
    const int grid = (npts + PTS - 1) / PTS;
    sdf_fused<<<grid, BLK, smem_bytes>>>(tables, W0, W1, W2, out, npts, lp);
}